// round 4
// baseline (speedup 1.0000x reference)
#include <cuda_runtime.h>
#include <cstdint>

// Problem shape (fixed by the dataset)
#define Bn 16
#define Hn 64
#define Wn 64
#define Cn 256
#define OHn 128
#define OWn 128
#define FLAT_PER_BATCH ((size_t)OHn * OWn * Cn)      // 4,194,304
#define IN_ELEMS ((size_t)Bn * Hn * Wn * Cn)         // 16,777,216
#define VEC_TOTAL (IN_ELEMS / 4)                     // 4,194,304
// vec4 chunks per batch = H*W*C/4 = 262,144 = 2^18  (NOT 2^20 — round-3 bug)

__global__ void __launch_bounds__(256)
maxunpool_scatter_kernel(const float4* __restrict__ upd,
                         const void* __restrict__ mask_raw,
                         float* __restrict__ out)
{
    unsigned v = blockIdx.x * blockDim.x + threadIdx.x;   // vec4 index
    if (v >= VEC_TOTAL) return;

    float4 u = upd[v];
    unsigned b = v >> 18;                                  // batch = v / 2^18
    float* ob = out + (size_t)b * FLAT_PER_BATCH;

    // Dtype probe: word[1] of the mask buffer. For this mask's structure,
    // element 1 has value 1. int32 layout -> word[1] == 1; int64 (LE) layout
    // -> word[1] == high half of element 0 == 0. Warp-uniform, L1-broadcast.
    int probe = __ldg((const int*)mask_raw + 1);

    if (probe != 0) {
        // ---- int32 mask: 4 indices in one 16B load ----
        int4 m = __ldg((const int4*)mask_raw + v);
        if (m.y == m.x + 1 && m.z == m.x + 2 && m.w == m.x + 3 &&
            (m.x & 3) == 0) {
            *reinterpret_cast<float4*>(ob + (unsigned)m.x) = u;   // STG.128
        } else {
            ob[(unsigned)m.x] = u.x;
            ob[(unsigned)m.y] = u.y;
            ob[(unsigned)m.z] = u.z;
            ob[(unsigned)m.w] = u.w;
        }
    } else {
        // ---- int64 mask: 4 indices in two 16B loads ----
        const ulonglong2* m64 = (const ulonglong2*)mask_raw;
        ulonglong2 m01 = __ldg(m64 + 2u * v);
        ulonglong2 m23 = __ldg(m64 + 2u * v + 1u);
        unsigned long long m0 = m01.x;
        if (m01.y == m0 + 1ull && m23.x == m0 + 2ull && m23.y == m0 + 3ull &&
            ((unsigned)m0 & 3u) == 0u) {
            *reinterpret_cast<float4*>(ob + (size_t)m0) = u;      // STG.128
        } else {
            ob[(size_t)m01.x] = u.x;
            ob[(size_t)m01.y] = u.y;
            ob[(size_t)m23.x] = u.z;
            ob[(size_t)m23.y] = u.w;
        }
    }
}

extern "C" void kernel_launch(void* const* d_in, const int* in_sizes, int n_in,
                              void* d_out, int out_size)
{
    const float4* upd = reinterpret_cast<const float4*>(d_in[0]);
    const void* mask = d_in[1];
    float* out = reinterpret_cast<float*>(d_out);

    // Zero-fill the output (scatter only touches 25% of it).
    cudaMemsetAsync(d_out, 0, (size_t)out_size * sizeof(float));

    const int threads = 256;
    const int blocks = (int)(VEC_TOTAL / threads);        // 16384
    maxunpool_scatter_kernel<<<blocks, threads>>>(upd, mask, out);
}

// round 5
// speedup vs baseline: 1.1329x; 1.1329x over previous
#include <cuda_runtime.h>
#include <cstdint>

// Problem shape (fixed by the dataset)
#define Bn 16
#define Hn 64
#define Wn 64
#define Cn 256
#define OHn 128
#define OWn 128
#define FLAT_PER_BATCH ((size_t)OHn * OWn * Cn)   // 4,194,304 floats
#define SRC_VEC ((size_t)Bn * Hn * Wn * Cn / 4)   // 4,194,304 vec4 sources
// v layout: c4 = v & 63, w = (v>>6) & 63, h = (v>>12) & 63, b = v >> 18

__device__ __forceinline__ float4 sel4(const int4 m, const float4 u, int flat)
{
    float4 r;
    r.x = (m.x == flat + 0) ? u.x : 0.0f;
    r.y = (m.y == flat + 1) ? u.y : 0.0f;
    r.z = (m.z == flat + 2) ? u.z : 0.0f;
    r.w = (m.w == flat + 3) ? u.w : 0.0f;
    return r;
}

// Gather-style unpool: each thread owns one source (h,w,c4) and writes its
// entire 2x2 output window (4 x float4). Valid argmax masks always point
// inside their own window at the same channel, so every output element is
// written exactly once (value if selected, else zero). No memset needed.
__global__ void __launch_bounds__(256)
maxunpool_gather_kernel(const float4* __restrict__ upd,
                        const int4* __restrict__ mask,
                        float4* __restrict__ out)
{
    unsigned v = blockIdx.x * blockDim.x + threadIdx.x;
    if (v >= SRC_VEC) return;

    float4 u = upd[v];
    int4 m = mask[v];

    unsigned c4 = v & 63u;            // channel / 4
    unsigned w  = (v >> 6) & 63u;
    unsigned h  = (v >> 12) & 63u;
    unsigned b  = v >> 18;

    unsigned oh = h * 2u, ow = w * 2u;
    // flat index of (oh, ow, 4*c4) within the batch
    int flat00 = (int)(((oh * OWn) + ow) * Cn + 4u * c4);
    int flat01 = flat00 + Cn;                 // (oh, ow+1)
    int flat10 = flat00 + OWn * Cn;           // (oh+1, ow)
    int flat11 = flat10 + Cn;                 // (oh+1, ow+1)

    float4* ob = out + (b * FLAT_PER_BATCH) / 4;
    ob[flat00 >> 2] = sel4(m, u, flat00);
    ob[flat01 >> 2] = sel4(m, u, flat01);
    ob[flat10 >> 2] = sel4(m, u, flat10);
    ob[flat11 >> 2] = sel4(m, u, flat11);
}

extern "C" void kernel_launch(void* const* d_in, const int* in_sizes, int n_in,
                              void* d_out, int out_size)
{
    const float4* upd = reinterpret_cast<const float4*>(d_in[0]);
    const int4* mask = reinterpret_cast<const int4*>(d_in[1]);
    float4* out = reinterpret_cast<float4*>(d_out);

    const int threads = 256;
    const int blocks = (int)(SRC_VEC / threads);   // 16384
    maxunpool_gather_kernel<<<blocks, threads>>>(upd, mask, out);
}